// round 7
// baseline (speedup 1.0000x reference)
#include <cuda_runtime.h>
#include <cuda_bf16.h>
#include <math.h>
#include <stdint.h>

// ---------------------------------------------------------------------------
// Problem constants
// ---------------------------------------------------------------------------
#define BATCH 2048
#define SEQT  20
#define M_TOK (BATCH*SEQT)   // 40960 tokens
#define NHEAD 4
#define HEADD 64
#define NCLS  1000
#define NLAYER 2

// ---------------------------------------------------------------------------
// Scratch
// ---------------------------------------------------------------------------
__device__ float g_buf1[(size_t)M_TOK * 1024];
__device__ float g_buf2[(size_t)M_TOK * 256];
__device__ float g_hst [(size_t)M_TOK * 256];
__device__ float g_wn  [(size_t)NCLS  * 256];

// ---------------------------------------------------------------------------
// Helpers
// ---------------------------------------------------------------------------
__device__ __forceinline__ float geluf(float x) {
    return 0.5f * x * (1.0f + erff(x * 0.7071067811865475f));
}
__device__ __forceinline__ float warp_sum(float v) {
    #pragma unroll
    for (int o = 16; o; o >>= 1) v += __shfl_xor_sync(0xffffffffu, v, o);
    return v;
}
__device__ __forceinline__ uint32_t smem_u32(const void* p) {
    uint32_t a;
    asm("{ .reg .u64 t; cvta.to.shared.u64 t, %1; cvt.u32.u64 %0, t; }" : "=r"(a) : "l"(p));
    return a;
}
__device__ __forceinline__ void ldsm4(uint32_t (&r)[4], uint32_t addr) {
    asm volatile("ldmatrix.sync.aligned.m8n8.x4.shared.b16 {%0,%1,%2,%3}, [%4];"
                 : "=r"(r[0]), "=r"(r[1]), "=r"(r[2]), "=r"(r[3]) : "r"(addr));
}
__device__ __forceinline__ void mma16816(float (&d)[4], const uint32_t (&a)[4],
                                         const uint32_t* b) {
    asm volatile("mma.sync.aligned.m16n8k16.row.col.f32.bf16.bf16.f32 "
                 "{%0,%1,%2,%3}, {%4,%5,%6,%7}, {%8,%9}, {%0,%1,%2,%3};"
                 : "+f"(d[0]), "+f"(d[1]), "+f"(d[2]), "+f"(d[3])
                 : "r"(a[0]), "r"(a[1]), "r"(a[2]), "r"(a[3]),
                   "r"(b[0]), "r"(b[1]));
}

// ---------------------------------------------------------------------------
// Split-bf16 tensor-core GEMM: C[M,N] = A[M,K] @ W[N,K]^T (+bias, epilogue)
//   EPI 0: +bias   EPI 1: gelu(+bias)   EPI 2: *scale (no bias)
// CTA 128x256, K-chunk 32 fp32, 3-pass split (AhWh + AlWh + AhWl),
// 512 threads = 16 warps (4 M x 4 N), warp tile 32x64, mma.m16n8k16 bf16.
// Double-buffered smem, register prefetch, ONE sync per chunk.
// Requires: M%128==0, K%32==0, N%2==0.
// ---------------------------------------------------------------------------
// smem per stage: Ah,Al = 128 rows x 80B; Wh,Wl = 256 rows x 80B
#define ROWB   80            // bytes per smem row (40 bf16: 32 data + 8 pad)
#define OFF_AH 0
#define OFF_AL 10240
#define OFF_WH 20480
#define OFF_WL 40960
#define STAGE  61440
#define SMEM_DYN (2*STAGE)   // 122880 B

template<int EPI>
__global__ __launch_bounds__(512, 1)
void gemm_mma(const float* __restrict__ A, const float* __restrict__ W,
              const float* __restrict__ bias, float* __restrict__ C,
              int M, int N, int K, float scale)
{
    extern __shared__ __align__(128) char smem[];
    const uint32_t sb = smem_u32(smem);
    const int tid  = threadIdx.x;
    const int wid  = tid >> 5;
    const int lane = tid & 31;
    const int bm = blockIdx.y * 128;
    const int bn = blockIdx.x * 256;
    const int wm = (wid & 3) * 32;     // warp row offset in tile
    const int wn = (wid >> 2) * 64;    // warp col offset in tile

    float acc[2][8][4];
    #pragma unroll
    for (int mi = 0; mi < 2; mi++)
        #pragma unroll
        for (int ni = 0; ni < 8; ni++)
            #pragma unroll
            for (int e = 0; e < 4; e++) acc[mi][ni][e] = 0.f;

    // prefetch: A = 128*32 fp32 = 1024 float4 (2/thread), W = 256*32 = 2048 (4/thread)
    float4 pa[2], pw[4];
    auto gload = [&](int c) {
        const float* Ab = A + (size_t)bm * K + (c << 5);
        const float* Wb = W + (c << 5);
        #pragma unroll
        for (int i = 0; i < 2; i++) {
            int fi = tid + 512 * i;
            int row = fi >> 3, c4 = (fi & 7) << 2;
            pa[i] = *(const float4*)(Ab + (size_t)row * K + c4);
        }
        #pragma unroll
        for (int i = 0; i < 4; i++) {
            int fi = tid + 512 * i;
            int row = fi >> 3, c4 = (fi & 7) << 2;
            int gn = bn + row;
            pw[i] = (gn < N) ? *(const float4*)(Wb + (size_t)gn * K + c4)
                             : make_float4(0.f, 0.f, 0.f, 0.f);
        }
    };
    auto split8 = [&](float4 v, uint2& hi, uint2& lo) {
        __nv_bfloat162 h01 = __floats2bfloat162_rn(v.x, v.y);
        __nv_bfloat162 h23 = __floats2bfloat162_rn(v.z, v.w);
        float2 f01 = __bfloat1622float2(h01);
        float2 f23 = __bfloat1622float2(h23);
        __nv_bfloat162 l01 = __floats2bfloat162_rn(v.x - f01.x, v.y - f01.y);
        __nv_bfloat162 l23 = __floats2bfloat162_rn(v.z - f23.x, v.w - f23.y);
        hi.x = *(uint32_t*)&h01; hi.y = *(uint32_t*)&h23;
        lo.x = *(uint32_t*)&l01; lo.y = *(uint32_t*)&l23;
    };
    auto sstore = [&](int s) {
        char* st = smem + s * STAGE;
        #pragma unroll
        for (int i = 0; i < 2; i++) {
            int fi = tid + 512 * i;
            int row = fi >> 3, c4 = (fi & 7) << 2;
            uint32_t off = row * ROWB + c4 * 2;
            uint2 hi, lo;
            split8(pa[i], hi, lo);
            *(uint2*)(st + OFF_AH + off) = hi;
            *(uint2*)(st + OFF_AL + off) = lo;
        }
        #pragma unroll
        for (int i = 0; i < 4; i++) {
            int fi = tid + 512 * i;
            int row = fi >> 3, c4 = (fi & 7) << 2;
            uint32_t off = row * ROWB + c4 * 2;
            uint2 hi, lo;
            split8(pw[i], hi, lo);
            *(uint2*)(st + OFF_WH + off) = hi;
            *(uint2*)(st + OFF_WL + off) = lo;
        }
    };

    // ldmatrix lane addressing
    const uint32_t a_row = wm + (lane & 15);
    const uint32_t a_kof = (lane >> 4) << 3;
    const uint32_t b_row = wn + (lane & 7) + (((lane >> 4) & 1) << 3);
    const uint32_t b_kof = ((lane >> 3) & 1) << 3;

    auto mma_pass = [&](uint32_t a_base, uint32_t w_base) {
        #pragma unroll
        for (int ks = 0; ks < 2; ks++) {
            const uint32_t k0 = ks << 4;
            uint32_t af[2][4];
            #pragma unroll
            for (int mi = 0; mi < 2; mi++)
                ldsm4(af[mi], a_base + (a_row + mi * 16) * ROWB + (k0 + a_kof) * 2);
            uint32_t bf[8][2];
            #pragma unroll
            for (int nj = 0; nj < 4; nj++) {
                uint32_t r[4];
                ldsm4(r, w_base + (b_row + nj * 16) * ROWB + (k0 + b_kof) * 2);
                bf[2*nj][0] = r[0]; bf[2*nj][1] = r[1];
                bf[2*nj+1][0] = r[2]; bf[2*nj+1][1] = r[3];
            }
            #pragma unroll
            for (int mi = 0; mi < 2; mi++)
                #pragma unroll
                for (int ni = 0; ni < 8; ni++)
                    mma16816(acc[mi][ni], af[mi], bf[ni]);
        }
    };

    const int nch = K >> 5;
    gload(0);
    sstore(0);
    __syncthreads();
    for (int c = 0; c < nch; c++) {
        if (c + 1 < nch) gload(c + 1);      // LDGs in flight during MMA
        const uint32_t st = sb + (c & 1) * STAGE;
        mma_pass(st + OFF_AH, st + OFF_WH);
        mma_pass(st + OFF_AL, st + OFF_WH);
        mma_pass(st + OFF_AH, st + OFF_WL);
        if (c + 1 < nch) {
            sstore((c + 1) & 1);            // other stage: free since sync at c-1
            __syncthreads();
        }
    }

    // epilogue
    const int r0 = lane >> 2;
    const int cc0 = (lane & 3) << 1;
    #pragma unroll
    for (int mi = 0; mi < 2; mi++) {
        #pragma unroll
        for (int ni = 0; ni < 8; ni++) {
            int col = bn + wn + ni * 8 + cc0;
            if (col >= N) continue;
            float b0 = 0.f, b1 = 0.f;
            if (EPI != 2 && bias != nullptr) { b0 = bias[col]; b1 = bias[col + 1]; }
            int row = bm + wm + mi * 16 + r0;
            #pragma unroll
            for (int h = 0; h < 2; h++) {
                float t0 = acc[mi][ni][2*h + 0] + b0;
                float t1 = acc[mi][ni][2*h + 1] + b1;
                if (EPI == 1) { t0 = geluf(t0); t1 = geluf(t1); }
                if (EPI == 2) { t0 *= scale; t1 *= scale; }
                float2 o; o.x = t0; o.y = t1;
                *(float2*)(C + (size_t)(row + 8*h) * N + col) = o;
            }
        }
    }
}

// ---------------------------------------------------------------------------
// Elementwise kernels
// ---------------------------------------------------------------------------
__global__ void ln_gelu_1024(float* __restrict__ buf,
                             const float* __restrict__ w,
                             const float* __restrict__ b)
{
    int row = blockIdx.x;
    float4* p = (float4*)(buf + (size_t)row * 1024);
    int tid = threadIdx.x;
    float4 x = p[tid];
    float s  = x.x + x.y + x.z + x.w;
    float ss = x.x*x.x + x.y*x.y + x.z*x.z + x.w*x.w;
    __shared__ float sh[2][8];
    float ws_ = warp_sum(s), wss = warp_sum(ss);
    if ((tid & 31) == 0) { sh[0][tid >> 5] = ws_; sh[1][tid >> 5] = wss; }
    __syncthreads();
    float tot = 0.f, tot2 = 0.f;
    #pragma unroll
    for (int i = 0; i < 8; i++) { tot += sh[0][i]; tot2 += sh[1][i]; }
    float mean = tot * (1.f / 1024.f);
    float var  = tot2 * (1.f / 1024.f) - mean * mean;
    float rstd = rsqrtf(var + 1e-6f);
    float4 wv = ((const float4*)w)[tid];
    float4 bv = ((const float4*)b)[tid];
    x.x = geluf((x.x - mean) * rstd * wv.x + bv.x);
    x.y = geluf((x.y - mean) * rstd * wv.y + bv.y);
    x.z = geluf((x.z - mean) * rstd * wv.z + bv.z);
    x.w = geluf((x.w - mean) * rstd * wv.w + bv.w);
    p[tid] = x;
}

__global__ void ln_pe_256(const float* __restrict__ src, float* __restrict__ dst,
                          const float* __restrict__ w, const float* __restrict__ b)
{
    int row  = blockIdx.x * 8 + (threadIdx.x >> 5);
    int lane = threadIdx.x & 31;
    const float* x = src + (size_t)row * 256;
    float v[8], s = 0.f, ss = 0.f;
    #pragma unroll
    for (int i = 0; i < 8; i++) { v[i] = x[lane + 32*i]; s += v[i]; ss += v[i]*v[i]; }
    s = warp_sum(s); ss = warp_sum(ss);
    float mean = s * (1.f/256.f);
    float var  = ss * (1.f/256.f) - mean*mean;
    float rstd = rsqrtf(var + 1e-6f);
    int t = row % SEQT;
    float* o = dst + (size_t)row * 256;
    #pragma unroll
    for (int i = 0; i < 8; i++) {
        int c = lane + 32*i;
        int j = c & ~1;
        float ang = (float)t * expf((float)j * (-9.210340371976184f / 256.f));
        float pe  = (c & 1) ? cosf(ang) : sinf(ang);
        o[c] = (v[i] - mean) * rstd * w[c] + b[c] + pe;
    }
}

__global__ void resln_256(float* __restrict__ h, const float* __restrict__ r,
                          const float* __restrict__ w, const float* __restrict__ b)
{
    int row  = blockIdx.x * 8 + (threadIdx.x >> 5);
    int lane = threadIdx.x & 31;
    float* hp = h + (size_t)row * 256;
    const float* rp = r + (size_t)row * 256;
    float v[8], s = 0.f, ss = 0.f;
    #pragma unroll
    for (int i = 0; i < 8; i++) {
        int c = lane + 32*i;
        v[i] = hp[c] + rp[c];
        s += v[i]; ss += v[i]*v[i];
    }
    s = warp_sum(s); ss = warp_sum(ss);
    float mean = s * (1.f/256.f);
    float var  = ss * (1.f/256.f) - mean*mean;
    float rstd = rsqrtf(var + 1e-6f);
    #pragma unroll
    for (int i = 0; i < 8; i++) {
        int c = lane + 32*i;
        hp[c] = (v[i] - mean) * rstd * w[c] + b[c];
    }
}

__global__ void norm_rows_256(const float* __restrict__ src, float* __restrict__ dst,
                              int nrows)
{
    int row  = blockIdx.x * 8 + (threadIdx.x >> 5);
    int lane = threadIdx.x & 31;
    if (row >= nrows) return;
    const float* x = src + (size_t)row * 256;
    float v[8], ss = 0.f;
    #pragma unroll
    for (int i = 0; i < 8; i++) { v[i] = x[lane + 32*i]; ss += v[i]*v[i]; }
    ss = warp_sum(ss);
    float inv = 1.f / fmaxf(sqrtf(ss), 1e-12f);
    float* o = dst + (size_t)row * 256;
    #pragma unroll
    for (int i = 0; i < 8; i++) o[lane + 32*i] = v[i] * inv;
}

__global__ void attn_kernel(const float* __restrict__ qkv, float* __restrict__ out)
{
    int bh = blockIdx.x;
    int bidx = bh / NHEAD;
    int hh   = bh % NHEAD;
    __shared__ float q[SEQT][HEADD];
    __shared__ float k[SEQT][HEADD];
    __shared__ float v[SEQT][HEADD];
    __shared__ float p[SEQT][SEQT];
    int tid = threadIdx.x;

    for (int idx = tid; idx < SEQT * HEADD; idx += 256) {
        int t = idx / HEADD, d = idx % HEADD;
        size_t off = (size_t)(bidx * SEQT + t) * 768 + hh * HEADD + d;
        q[t][d] = qkv[off];
        k[t][d] = qkv[off + 256];
        v[t][d] = qkv[off + 512];
    }
    __syncthreads();

    for (int idx = tid; idx < SEQT * SEQT; idx += 256) {
        int t = idx / SEQT, s = idx % SEQT;
        if (s <= t) {
            float acc = 0.f;
            #pragma unroll
            for (int d = 0; d < HEADD; d++) acc += q[t][d] * k[s][d];
            p[t][s] = acc * 0.125f;
        } else p[t][s] = 0.f;
    }
    __syncthreads();

    if (tid < SEQT) {
        int t = tid;
        float mx = -1e30f;
        for (int s = 0; s <= t; s++) mx = fmaxf(mx, p[t][s]);
        float sum = 0.f;
        for (int s = 0; s <= t; s++) { float e = expf(p[t][s] - mx); p[t][s] = e; sum += e; }
        float inv = 1.f / sum;
        for (int s = 0; s <= t; s++) p[t][s] *= inv;
        for (int s = t + 1; s < SEQT; s++) p[t][s] = 0.f;
    }
    __syncthreads();

    for (int idx = tid; idx < SEQT * HEADD; idx += 256) {
        int t = idx / HEADD, d = idx % HEADD;
        float acc = 0.f;
        for (int s = 0; s <= t; s++) acc += p[t][s] * v[s][d];
        out[(size_t)(bidx * SEQT + t) * 256 + hh * HEADD + d] = acc;
    }
}

// ---------------------------------------------------------------------------
// Launch
// ---------------------------------------------------------------------------
extern "C" void kernel_launch(void* const* d_in, const int* in_sizes, int n_in,
                              void* d_out, int out_size)
{
    const float* x         = (const float*)d_in[0];
    const float* p1_w      = (const float*)d_in[1];
    const float* p1_b      = (const float*)d_in[2];
    const float* pln1_w    = (const float*)d_in[3];
    const float* pln1_b    = (const float*)d_in[4];
    const float* p2_w      = (const float*)d_in[5];
    const float* pln2_w    = (const float*)d_in[6];
    const float* pln2_b    = (const float*)d_in[7];
    const float* in_proj_w = (const float*)d_in[8];
    const float* in_proj_b = (const float*)d_in[9];
    const float* out_proj_w= (const float*)d_in[10];
    const float* out_proj_b= (const float*)d_in[11];
    const float* ln1_w     = (const float*)d_in[12];
    const float* ln1_b     = (const float*)d_in[13];
    const float* lin1_w    = (const float*)d_in[14];
    const float* lin1_b    = (const float*)d_in[15];
    const float* lin2_w    = (const float*)d_in[16];
    const float* lin2_b    = (const float*)d_in[17];
    const float* ln2_w     = (const float*)d_in[18];
    const float* ln2_b     = (const float*)d_in[19];
    const float* head_w    = (const float*)d_in[20];
    float* out = (float*)d_out;

    float *b1, *b2, *h, *wn;
    cudaGetSymbolAddress((void**)&b1, g_buf1);
    cudaGetSymbolAddress((void**)&b2, g_buf2);
    cudaGetSymbolAddress((void**)&h,  g_hst);
    cudaGetSymbolAddress((void**)&wn, g_wn);

    cudaFuncSetAttribute(gemm_mma<0>, cudaFuncAttributeMaxDynamicSharedMemorySize, SMEM_DYN);
    cudaFuncSetAttribute(gemm_mma<1>, cudaFuncAttributeMaxDynamicSharedMemorySize, SMEM_DYN);
    cudaFuncSetAttribute(gemm_mma<2>, cudaFuncAttributeMaxDynamicSharedMemorySize, SMEM_DYN);

    const int M = M_TOK;
    const dim3 blk5(512);
    const dim3 blk(256);
    const int MB = M / 128;  // 320
    #define GRID(N_) dim3(((N_) + 255) / 256, MB)

    // projector
    gemm_mma<0><<<GRID(1024), blk5, SMEM_DYN>>>(x, p1_w, p1_b, b1, M, 1024, 2048, 1.f);
    ln_gelu_1024<<<M, blk>>>(b1, pln1_w, pln1_b);
    gemm_mma<0><<<GRID(256), blk5, SMEM_DYN>>>(b1, p2_w, nullptr, b2, M, 256, 1024, 1.f);
    ln_pe_256<<<M / 8, blk>>>(b2, h, pln2_w, pln2_b);

    // transformer layers
    for (int i = 0; i < NLAYER; i++) {
        const float* ipw = in_proj_w + (size_t)i * 768 * 256;
        const float* ipb = in_proj_b + (size_t)i * 768;
        const float* opw = out_proj_w + (size_t)i * 256 * 256;
        const float* opb = out_proj_b + (size_t)i * 256;
        const float* l1w = lin1_w + (size_t)i * 1024 * 256;
        const float* l1b = lin1_b + (size_t)i * 1024;
        const float* l2w = lin2_w + (size_t)i * 256 * 1024;
        const float* l2b = lin2_b + (size_t)i * 256;

        gemm_mma<0><<<GRID(768), blk5, SMEM_DYN>>>(h, ipw, ipb, b1, M, 768, 256, 1.f);
        attn_kernel<<<BATCH * NHEAD, blk>>>(b1, b2);
        gemm_mma<0><<<GRID(256), blk5, SMEM_DYN>>>(b2, opw, opb, b1, M, 256, 256, 1.f);
        resln_256<<<M / 8, blk>>>(h, b1, ln1_w + (size_t)i * 256, ln1_b + (size_t)i * 256);
        gemm_mma<1><<<GRID(1024), blk5, SMEM_DYN>>>(h, l1w, l1b, b1, M, 1024, 256, 1.f);
        gemm_mma<0><<<GRID(256), blk5, SMEM_DYN>>>(b1, l2w, l2b, b2, M, 256, 1024, 1.f);
        resln_256<<<M / 8, blk>>>(h, b2, ln2_w + (size_t)i * 256, ln2_b + (size_t)i * 256);
    }

    // cosine head
    norm_rows_256<<<M / 8, blk>>>(h, b2, M);
    norm_rows_256<<<(NCLS + 7) / 8, blk>>>(head_w, wn, NCLS);
    gemm_mma<2><<<GRID(NCLS), blk5, SMEM_DYN>>>(b2, wn, nullptr, out, M, NCLS, 256, 10.f);
}

// round 11
// speedup vs baseline: 1.3936x; 1.3936x over previous
#include <cuda_runtime.h>
#include <cuda_bf16.h>
#include <math.h>
#include <stdint.h>

// ---------------------------------------------------------------------------
// Problem constants
// ---------------------------------------------------------------------------
#define BATCH 2048
#define SEQT  20
#define M_TOK (BATCH*SEQT)   // 40960 tokens
#define NHEAD 4
#define HEADD 64
#define NCLS  1000
#define NLAYER 2

// ---------------------------------------------------------------------------
// Scratch
// ---------------------------------------------------------------------------
__device__ float g_buf1[(size_t)M_TOK * 1024];
__device__ float g_buf2[(size_t)M_TOK * 256];
__device__ float g_hst [(size_t)M_TOK * 256];
__device__ float g_wn  [(size_t)NCLS  * 256];

// ---------------------------------------------------------------------------
// Helpers
// ---------------------------------------------------------------------------
__device__ __forceinline__ float geluf(float x) {
    return 0.5f * x * (1.0f + erff(x * 0.7071067811865475f));
}
__device__ __forceinline__ float warp_sum(float v) {
    #pragma unroll
    for (int o = 16; o; o >>= 1) v += __shfl_xor_sync(0xffffffffu, v, o);
    return v;
}
__device__ __forceinline__ uint32_t smem_u32(const void* p) {
    uint32_t a;
    asm("{ .reg .u64 t; cvta.to.shared.u64 t, %1; cvt.u32.u64 %0, t; }" : "=r"(a) : "l"(p));
    return a;
}
__device__ __forceinline__ void ldsm4(uint32_t (&r)[4], uint32_t addr) {
    asm volatile("ldmatrix.sync.aligned.m8n8.x4.shared.b16 {%0,%1,%2,%3}, [%4];"
                 : "=r"(r[0]), "=r"(r[1]), "=r"(r[2]), "=r"(r[3]) : "r"(addr));
}
__device__ __forceinline__ void mma16816(float (&d)[4], const uint32_t (&a)[4],
                                         const uint32_t* b) {
    asm volatile("mma.sync.aligned.m16n8k16.row.col.f32.bf16.bf16.f32 "
                 "{%0,%1,%2,%3}, {%4,%5,%6,%7}, {%8,%9}, {%0,%1,%2,%3};"
                 : "+f"(d[0]), "+f"(d[1]), "+f"(d[2]), "+f"(d[3])
                 : "r"(a[0]), "r"(a[1]), "r"(a[2]), "r"(a[3]),
                   "r"(b[0]), "r"(b[1]));
}

// ---------------------------------------------------------------------------
// Split-bf16 tensor-core GEMM: C[M,N] = A[M,K] @ W[N,K]^T (+bias, epilogue)
//   EPI 0: +bias   EPI 1: gelu(+bias)   EPI 2: *scale (no bias)
// CTA 128x128, K-chunk 32 fp32, 3-pass split (AhWh + AlWh + AhWl),
// 256 threads = 8 warps (4 M x 2 N), warp tile 32x64, mma.m16n8k16 bf16.
// 2 CTAs/SM (launch_bounds(256,2)), staggered A/W prefetch to stay <128 regs,
// single __syncthreads per chunk. M%128==0, K%32==0, N%2==0.
// ---------------------------------------------------------------------------
// smem per stage: Ah,Al,Wh,Wl each 128 rows x 80B = 10240B
#define ROWB   80            // bytes per smem row (40 bf16: 32 data + 8 pad)
#define OFF_AH 0
#define OFF_AL 10240
#define OFF_WH 20480
#define OFF_WL 30720
#define STAGE  40960
#define SMEM_DYN (2*STAGE)   // 81920 B -> 2 CTAs/SM = 163840 B

template<int EPI>
__global__ __launch_bounds__(256, 2)
void gemm_mma(const float* __restrict__ A, const float* __restrict__ W,
              const float* __restrict__ bias, float* __restrict__ C,
              int M, int N, int K, float scale)
{
    extern __shared__ __align__(128) char smem[];
    const uint32_t sb = smem_u32(smem);
    const int tid  = threadIdx.x;
    const int wid  = tid >> 5;
    const int lane = tid & 31;
    const int bm = blockIdx.y * 128;
    const int bn = blockIdx.x * 128;
    const int wm = (wid & 3) * 32;     // warp row offset in tile
    const int wn = (wid >> 2) * 64;    // warp col offset in tile

    float acc[2][8][4];
    #pragma unroll
    for (int mi = 0; mi < 2; mi++)
        #pragma unroll
        for (int ni = 0; ni < 8; ni++)
            #pragma unroll
            for (int e = 0; e < 4; e++) acc[mi][ni][e] = 0.f;

    // load indexing: 128 rows x 32 floats = 1024 float4 = 4/thread (each of A, W)
    const int l_row0 = tid >> 3;          // advances by 32 per i
    const int l_c4   = (tid & 7) << 2;

    float4 pf[4];
    auto gloadA = [&](int c) {
        const float* Ab = A + (size_t)bm * K + (c << 5);
        #pragma unroll
        for (int i = 0; i < 4; i++)
            pf[i] = *(const float4*)(Ab + (size_t)(l_row0 + 32 * i) * K + l_c4);
    };
    auto gloadW = [&](int c) {
        const float* Wb = W + (c << 5);
        #pragma unroll
        for (int i = 0; i < 4; i++) {
            int gn = bn + l_row0 + 32 * i;
            pf[i] = (gn < N) ? *(const float4*)(Wb + (size_t)gn * K + l_c4)
                             : make_float4(0.f, 0.f, 0.f, 0.f);
        }
    };
    auto split8 = [&](float4 v, uint2& hi, uint2& lo) {
        __nv_bfloat162 h01 = __floats2bfloat162_rn(v.x, v.y);
        __nv_bfloat162 h23 = __floats2bfloat162_rn(v.z, v.w);
        float2 f01 = __bfloat1622float2(h01);
        float2 f23 = __bfloat1622float2(h23);
        __nv_bfloat162 l01 = __floats2bfloat162_rn(v.x - f01.x, v.y - f01.y);
        __nv_bfloat162 l23 = __floats2bfloat162_rn(v.z - f23.x, v.w - f23.y);
        hi.x = *(uint32_t*)&h01; hi.y = *(uint32_t*)&h23;
        lo.x = *(uint32_t*)&l01; lo.y = *(uint32_t*)&l23;
    };
    auto sstoreA = [&](int s) {
        char* st = smem + s * STAGE;
        #pragma unroll
        for (int i = 0; i < 4; i++) {
            uint32_t off = (l_row0 + 32 * i) * ROWB + l_c4 * 2;
            uint2 hi, lo;
            split8(pf[i], hi, lo);
            *(uint2*)(st + OFF_AH + off) = hi;
            *(uint2*)(st + OFF_AL + off) = lo;
        }
    };
    auto sstoreW = [&](int s) {
        char* st = smem + s * STAGE;
        #pragma unroll
        for (int i = 0; i < 4; i++) {
            uint32_t off = (l_row0 + 32 * i) * ROWB + l_c4 * 2;
            uint2 hi, lo;
            split8(pf[i], hi, lo);
            *(uint2*)(st + OFF_WH + off) = hi;
            *(uint2*)(st + OFF_WL + off) = lo;
        }
    };

    // ldmatrix lane addressing
    const uint32_t a_row = wm + (lane & 15);
    const uint32_t a_kof = (lane >> 4) << 3;
    const uint32_t b_row = wn + (lane & 7) + (((lane >> 4) & 1) << 3);
    const uint32_t b_kof = ((lane >> 3) & 1) << 3;

    auto mma_pass = [&](uint32_t a_base, uint32_t w_base) {
        #pragma unroll
        for (int ks = 0; ks < 2; ks++) {
            const uint32_t k0 = ks << 4;
            uint32_t af[2][4];
            #pragma unroll
            for (int mi = 0; mi < 2; mi++)
                ldsm4(af[mi], a_base + (a_row + mi * 16) * ROWB + (k0 + a_kof) * 2);
            uint32_t bf[8][2];
            #pragma unroll
            for (int nj = 0; nj < 4; nj++) {
                uint32_t r[4];
                ldsm4(r, w_base + (b_row + nj * 16) * ROWB + (k0 + b_kof) * 2);
                bf[2*nj][0] = r[0]; bf[2*nj][1] = r[1];
                bf[2*nj+1][0] = r[2]; bf[2*nj+1][1] = r[3];
            }
            #pragma unroll
            for (int mi = 0; mi < 2; mi++)
                #pragma unroll
                for (int ni = 0; ni < 8; ni++)
                    mma16816(acc[mi][ni], af[mi], bf[ni]);
        }
    };

    const int nch = K >> 5;
    gloadA(0); sstoreA(0);
    gloadW(0); sstoreW(0);
    __syncthreads();
    for (int c = 0; c < nch; c++) {
        const uint32_t st = sb + (c & 1) * STAGE;
        const bool more = (c + 1 < nch);
        if (more) gloadA(c + 1);                 // LDGs fly over pass 1
        mma_pass(st + OFF_AH, st + OFF_WH);
        if (more) { sstoreA((c + 1) & 1); gloadW(c + 1); }
        mma_pass(st + OFF_AL, st + OFF_WH);
        if (more) sstoreW((c + 1) & 1);
        mma_pass(st + OFF_AH, st + OFF_WL);
        if (more) __syncthreads();
    }

    // epilogue
    const int r0 = lane >> 2;
    const int cc0 = (lane & 3) << 1;
    #pragma unroll
    for (int mi = 0; mi < 2; mi++) {
        #pragma unroll
        for (int ni = 0; ni < 8; ni++) {
            int col = bn + wn + ni * 8 + cc0;
            if (col >= N) continue;
            float b0 = 0.f, b1 = 0.f;
            if (EPI != 2 && bias != nullptr) { b0 = bias[col]; b1 = bias[col + 1]; }
            int row = bm + wm + mi * 16 + r0;
            #pragma unroll
            for (int h = 0; h < 2; h++) {
                float t0 = acc[mi][ni][2*h + 0] + b0;
                float t1 = acc[mi][ni][2*h + 1] + b1;
                if (EPI == 1) { t0 = geluf(t0); t1 = geluf(t1); }
                if (EPI == 2) { t0 *= scale; t1 *= scale; }
                float2 o; o.x = t0; o.y = t1;
                *(float2*)(C + (size_t)(row + 8*h) * N + col) = o;
            }
        }
    }
}

// ---------------------------------------------------------------------------
// Elementwise kernels
// ---------------------------------------------------------------------------
__global__ void ln_gelu_1024(float* __restrict__ buf,
                             const float* __restrict__ w,
                             const float* __restrict__ b)
{
    int row = blockIdx.x;
    float4* p = (float4*)(buf + (size_t)row * 1024);
    int tid = threadIdx.x;
    float4 x = p[tid];
    float s  = x.x + x.y + x.z + x.w;
    float ss = x.x*x.x + x.y*x.y + x.z*x.z + x.w*x.w;
    __shared__ float sh[2][8];
    float ws_ = warp_sum(s), wss = warp_sum(ss);
    if ((tid & 31) == 0) { sh[0][tid >> 5] = ws_; sh[1][tid >> 5] = wss; }
    __syncthreads();
    float tot = 0.f, tot2 = 0.f;
    #pragma unroll
    for (int i = 0; i < 8; i++) { tot += sh[0][i]; tot2 += sh[1][i]; }
    float mean = tot * (1.f / 1024.f);
    float var  = tot2 * (1.f / 1024.f) - mean * mean;
    float rstd = rsqrtf(var + 1e-6f);
    float4 wv = ((const float4*)w)[tid];
    float4 bv = ((const float4*)b)[tid];
    x.x = geluf((x.x - mean) * rstd * wv.x + bv.x);
    x.y = geluf((x.y - mean) * rstd * wv.y + bv.y);
    x.z = geluf((x.z - mean) * rstd * wv.z + bv.z);
    x.w = geluf((x.w - mean) * rstd * wv.w + bv.w);
    p[tid] = x;
}

__global__ void ln_pe_256(const float* __restrict__ src, float* __restrict__ dst,
                          const float* __restrict__ w, const float* __restrict__ b)
{
    int row  = blockIdx.x * 8 + (threadIdx.x >> 5);
    int lane = threadIdx.x & 31;
    const float* x = src + (size_t)row * 256;
    float v[8], s = 0.f, ss = 0.f;
    #pragma unroll
    for (int i = 0; i < 8; i++) { v[i] = x[lane + 32*i]; s += v[i]; ss += v[i]*v[i]; }
    s = warp_sum(s); ss = warp_sum(ss);
    float mean = s * (1.f/256.f);
    float var  = ss * (1.f/256.f) - mean*mean;
    float rstd = rsqrtf(var + 1e-6f);
    int t = row % SEQT;
    float* o = dst + (size_t)row * 256;
    #pragma unroll
    for (int i = 0; i < 8; i++) {
        int c = lane + 32*i;
        int j = c & ~1;
        float ang = (float)t * expf((float)j * (-9.210340371976184f / 256.f));
        float pe  = (c & 1) ? cosf(ang) : sinf(ang);
        o[c] = (v[i] - mean) * rstd * w[c] + b[c] + pe;
    }
}

__global__ void resln_256(float* __restrict__ h, const float* __restrict__ r,
                          const float* __restrict__ w, const float* __restrict__ b)
{
    int row  = blockIdx.x * 8 + (threadIdx.x >> 5);
    int lane = threadIdx.x & 31;
    float* hp = h + (size_t)row * 256;
    const float* rp = r + (size_t)row * 256;
    float v[8], s = 0.f, ss = 0.f;
    #pragma unroll
    for (int i = 0; i < 8; i++) {
        int c = lane + 32*i;
        v[i] = hp[c] + rp[c];
        s += v[i]; ss += v[i]*v[i];
    }
    s = warp_sum(s); ss = warp_sum(ss);
    float mean = s * (1.f/256.f);
    float var  = ss * (1.f/256.f) - mean*mean;
    float rstd = rsqrtf(var + 1e-6f);
    #pragma unroll
    for (int i = 0; i < 8; i++) {
        int c = lane + 32*i;
        hp[c] = (v[i] - mean) * rstd * w[c] + b[c];
    }
}

__global__ void norm_rows_256(const float* __restrict__ src, float* __restrict__ dst,
                              int nrows)
{
    int row  = blockIdx.x * 8 + (threadIdx.x >> 5);
    int lane = threadIdx.x & 31;
    if (row >= nrows) return;
    const float* x = src + (size_t)row * 256;
    float v[8], ss = 0.f;
    #pragma unroll
    for (int i = 0; i < 8; i++) { v[i] = x[lane + 32*i]; ss += v[i]*v[i]; }
    ss = warp_sum(ss);
    float inv = 1.f / fmaxf(sqrtf(ss), 1e-12f);
    float* o = dst + (size_t)row * 256;
    #pragma unroll
    for (int i = 0; i < 8; i++) o[lane + 32*i] = v[i] * inv;
}

__global__ void attn_kernel(const float* __restrict__ qkv, float* __restrict__ out)
{
    int bh = blockIdx.x;
    int bidx = bh / NHEAD;
    int hh   = bh % NHEAD;
    __shared__ float q[SEQT][HEADD];
    __shared__ float k[SEQT][HEADD];
    __shared__ float v[SEQT][HEADD];
    __shared__ float p[SEQT][SEQT];
    int tid = threadIdx.x;

    for (int idx = tid; idx < SEQT * HEADD; idx += 256) {
        int t = idx / HEADD, d = idx % HEADD;
        size_t off = (size_t)(bidx * SEQT + t) * 768 + hh * HEADD + d;
        q[t][d] = qkv[off];
        k[t][d] = qkv[off + 256];
        v[t][d] = qkv[off + 512];
    }
    __syncthreads();

    for (int idx = tid; idx < SEQT * SEQT; idx += 256) {
        int t = idx / SEQT, s = idx % SEQT;
        if (s <= t) {
            float acc = 0.f;
            #pragma unroll
            for (int d = 0; d < HEADD; d++) acc += q[t][d] * k[s][d];
            p[t][s] = acc * 0.125f;
        } else p[t][s] = 0.f;
    }
    __syncthreads();

    if (tid < SEQT) {
        int t = tid;
        float mx = -1e30f;
        for (int s = 0; s <= t; s++) mx = fmaxf(mx, p[t][s]);
        float sum = 0.f;
        for (int s = 0; s <= t; s++) { float e = expf(p[t][s] - mx); p[t][s] = e; sum += e; }
        float inv = 1.f / sum;
        for (int s = 0; s <= t; s++) p[t][s] *= inv;
        for (int s = t + 1; s < SEQT; s++) p[t][s] = 0.f;
    }
    __syncthreads();

    for (int idx = tid; idx < SEQT * HEADD; idx += 256) {
        int t = idx / HEADD, d = idx % HEADD;
        float acc = 0.f;
        for (int s = 0; s <= t; s++) acc += p[t][s] * v[s][d];
        out[(size_t)(bidx * SEQT + t) * 256 + hh * HEADD + d] = acc;
    }
}

// ---------------------------------------------------------------------------
// Launch
// ---------------------------------------------------------------------------
extern "C" void kernel_launch(void* const* d_in, const int* in_sizes, int n_in,
                              void* d_out, int out_size)
{
    const float* x         = (const float*)d_in[0];
    const float* p1_w      = (const float*)d_in[1];
    const float* p1_b      = (const float*)d_in[2];
    const float* pln1_w    = (const float*)d_in[3];
    const float* pln1_b    = (const float*)d_in[4];
    const float* p2_w      = (const float*)d_in[5];
    const float* pln2_w    = (const float*)d_in[6];
    const float* pln2_b    = (const float*)d_in[7];
    const float* in_proj_w = (const float*)d_in[8];
    const float* in_proj_b = (const float*)d_in[9];
    const float* out_proj_w= (const float*)d_in[10];
    const float* out_proj_b= (const float*)d_in[11];
    const float* ln1_w     = (const float*)d_in[12];
    const float* ln1_b     = (const float*)d_in[13];
    const float* lin1_w    = (const float*)d_in[14];
    const float* lin1_b    = (const float*)d_in[15];
    const float* lin2_w    = (const float*)d_in[16];
    const float* lin2_b    = (const float*)d_in[17];
    const float* ln2_w     = (const float*)d_in[18];
    const float* ln2_b     = (const float*)d_in[19];
    const float* head_w    = (const float*)d_in[20];
    float* out = (float*)d_out;

    float *b1, *b2, *h, *wn;
    cudaGetSymbolAddress((void**)&b1, g_buf1);
    cudaGetSymbolAddress((void**)&b2, g_buf2);
    cudaGetSymbolAddress((void**)&h,  g_hst);
    cudaGetSymbolAddress((void**)&wn, g_wn);

    cudaFuncSetAttribute(gemm_mma<0>, cudaFuncAttributeMaxDynamicSharedMemorySize, SMEM_DYN);
    cudaFuncSetAttribute(gemm_mma<1>, cudaFuncAttributeMaxDynamicSharedMemorySize, SMEM_DYN);
    cudaFuncSetAttribute(gemm_mma<2>, cudaFuncAttributeMaxDynamicSharedMemorySize, SMEM_DYN);

    const int M = M_TOK;
    const dim3 blk(256);
    const int MB = M / 128;  // 320
    #define GRID(N_) dim3(((N_) + 127) / 128, MB)

    // projector
    gemm_mma<0><<<GRID(1024), blk, SMEM_DYN>>>(x, p1_w, p1_b, b1, M, 1024, 2048, 1.f);
    ln_gelu_1024<<<M, blk>>>(b1, pln1_w, pln1_b);
    gemm_mma<0><<<GRID(256), blk, SMEM_DYN>>>(b1, p2_w, nullptr, b2, M, 256, 1024, 1.f);
    ln_pe_256<<<M / 8, blk>>>(b2, h, pln2_w, pln2_b);

    // transformer layers
    for (int i = 0; i < NLAYER; i++) {
        const float* ipw = in_proj_w + (size_t)i * 768 * 256;
        const float* ipb = in_proj_b + (size_t)i * 768;
        const float* opw = out_proj_w + (size_t)i * 256 * 256;
        const float* opb = out_proj_b + (size_t)i * 256;
        const float* l1w = lin1_w + (size_t)i * 1024 * 256;
        const float* l1b = lin1_b + (size_t)i * 1024;
        const float* l2w = lin2_w + (size_t)i * 256 * 1024;
        const float* l2b = lin2_b + (size_t)i * 256;

        gemm_mma<0><<<GRID(768), blk, SMEM_DYN>>>(h, ipw, ipb, b1, M, 768, 256, 1.f);
        attn_kernel<<<BATCH * NHEAD, blk>>>(b1, b2);
        gemm_mma<0><<<GRID(256), blk, SMEM_DYN>>>(b2, opw, opb, b1, M, 256, 256, 1.f);
        resln_256<<<M / 8, blk>>>(h, b1, ln1_w + (size_t)i * 256, ln1_b + (size_t)i * 256);
        gemm_mma<1><<<GRID(1024), blk, SMEM_DYN>>>(h, l1w, l1b, b1, M, 1024, 256, 1.f);
        gemm_mma<0><<<GRID(256), blk, SMEM_DYN>>>(b1, l2w, l2b, b2, M, 256, 1024, 1.f);
        resln_256<<<M / 8, blk>>>(h, b2, ln2_w + (size_t)i * 256, ln2_b + (size_t)i * 256);
    }

    // cosine head
    norm_rows_256<<<M / 8, blk>>>(h, b2, M);
    norm_rows_256<<<(NCLS + 7) / 8, blk>>>(head_w, wn, NCLS);
    gemm_mma<2><<<GRID(NCLS), blk, SMEM_DYN>>>(b2, wn, nullptr, out, M, NCLS, 256, 10.f);
}